// round 7
// baseline (speedup 1.0000x reference)
#include <cuda_runtime.h>
#include <math.h>

// SpatialPositionalEncoding2D: out[b,l,d] = x[b,l,d] + pe(l,d)
// h = w = 128, L = 16384, D = 256, dh = 128, b = 8.
//
// pe is separable AND symmetric: pe(l,d) = T[pos, j] where
//   d < 128 : pos = row(l), j = d/4   (quad index)
//   d >= 128: pos = col(l), j = (d-128)/4
// and T is the SAME 128x32-quad (64 KB) table for both halves. Build it with a
// tiny prologue kernel; it stays L2-hot. Main kernel uses R1's batch-8
// amortized buffering but with a table lookup instead of trig, cutting regs
// so 5 blocks/SM fit: 40 warps x MLP 8 = 320 in-flight loads per SM.

namespace {
constexpr int H  = 128;
constexpr int W  = 128;
constexpr int L  = H * W;       // 16384
constexpr int D  = 256;
constexpr int D4 = D / 4;       // 64 float4 per position
constexpr unsigned STRIDE4 = (unsigned)L * D4;     // float4 per batch image
constexpr int TABLE_QUADS = H * 32;                // 128 pos x 32 quads = 4096
constexpr int POS_PER_BLOCK = 4;                   // 256 thr = 4 pos x 64 quads
}

// g_pe4[pos*32 + j] = (sin(p f0), cos(p f0), sin(p f1), cos(p f1)),
// f0 = freq(2j), f1 = freq(2j+1), freq(k) = exp(k * -2 ln(10000)/128).
__device__ float4 g_pe4[TABLE_QUADS];

__global__ void pe_table_kernel()
{
    const int idx = blockIdx.x * blockDim.x + threadIdx.x;  // 0..4095
    const int pos = idx >> 5;        // 0..127
    const int q   = idx & 31;        // quad within half

    const float KF = -0.14391156831212787f;   // -2*ln(10000)/128
    const float f0 = expf((float)(2 * q)     * KF);
    const float f1 = expf((float)(2 * q + 1) * KF);

    float s0, c0, s1, c1;
    sincosf((float)pos * f0, &s0, &c0);
    sincosf((float)pos * f1, &s1, &c1);
    g_pe4[idx] = make_float4(s0, c0, s1, c1);
}

__global__ void __launch_bounds__(256, 5)
pe_add_kernel(const float4* __restrict__ x, float4* __restrict__ out, int b)
{
    const int tid = threadIdx.x;
    const int lq  = tid & (D4 - 1);                          // 0..63
    const int l   = (blockIdx.x << 2) + (tid >> 6);          // position

    const int row = l >> 7;
    const int col = l & (W - 1);

    // One hot-table lookup replaces all trig. Lanes with lq<32 read the row
    // entry, lanes lq>=32 the col entry: each warp-half reads 512 contiguous B.
    const int tidx = (lq < 32) ? ((row << 5) + lq)
                               : ((col << 5) + lq - 32);
    const float4 pe = __ldg(&g_pe4[tidx]);

    const unsigned base = (unsigned)l * D4 + (unsigned)lq;   // fits 32-bit

    if (b == 8) {
        // All 8 loads in flight before any store (MLP=8 per thread).
        float4 v[8];
        #pragma unroll
        for (int bi = 0; bi < 8; bi++)
            v[bi] = x[base + bi * STRIDE4];
        #pragma unroll
        for (int bi = 0; bi < 8; bi++) {
            v[bi].x += pe.x; v[bi].y += pe.y; v[bi].z += pe.z; v[bi].w += pe.w;
            out[base + bi * STRIDE4] = v[bi];
        }
    } else {
        for (int bi = 0; bi < b; bi++) {
            float4 v = x[base + bi * STRIDE4];
            v.x += pe.x; v.y += pe.y; v.z += pe.z; v.w += pe.w;
            out[base + bi * STRIDE4] = v;
        }
    }
}

extern "C" void kernel_launch(void* const* d_in, const int* in_sizes, int n_in,
                              void* d_out, int out_size)
{
    const float4* x  = (const float4*)d_in[0];
    float4* out      = (float4*)d_out;
    const int n      = in_sizes[0];          // total elements of x
    const int b      = n / (L * D);          // batch size (8 here)

    pe_table_kernel<<<TABLE_QUADS / 256, 256>>>();           // 16 blocks, ~1us

    const dim3 grid(L / POS_PER_BLOCK);                      // 4096 blocks
    const dim3 block(256);
    pe_add_kernel<<<grid, block>>>(x, out, b);
}

// round 8
// speedup vs baseline: 1.0214x; 1.0214x over previous
#include <cuda_runtime.h>
#include <math.h>

// SpatialPositionalEncoding2D: out[b,l,d] = x[b,l,d] + pe(l,d)
// h = w = 128, L = 16384, D = 256, dh = 128, b = 8.
// pe(l, d):
//   row = l / 128, col = l % 128
//   d <  128: j = d/2,        arg = row * freq[j]
//   d >= 128: j = (d-128)/2,  arg = col * freq[j]
//   freq[j] = exp(-2*j * ln(10000)/128); even d -> sin, odd d -> cos.
//
// FINAL FORM (session conclusion): this kernel is pinned at the GB300 mixed
// read+write HBM streaming ceiling (~5.9 TB/s, 74-75% of read spec). Seven
// structural variants (occupancy 41-84%, MLP 1-8, inline trig vs L2-hot table,
// contiguous vs batch-strided access, ldcg/ldcs/evict_last/stcs policies) all
// measured 36.4-37.5 us for the main kernel; none moved DRAM% out of the
// 71-75% band. The winning configuration is the simplest: one launch, inline
// trig amortized over the 8-image batch (trig cost: fma pipe <8%), batch-8
// load buffering, float4 accesses, default cache policy.

namespace {
constexpr int H  = 128;
constexpr int W  = 128;
constexpr int L  = H * W;     // 16384
constexpr int D  = 256;
constexpr int D4 = D / 4;     // 64 float4 per position
constexpr unsigned STRIDE4 = (unsigned)L * D4;   // float4 per batch image
constexpr int POS_PER_BLOCK = 4;   // 256 threads = 4 positions x 64 quads
}

__global__ void __launch_bounds__(256, 4)
pe_add_kernel(const float4* __restrict__ x, float4* __restrict__ out, int b)
{
    const int tid = threadIdx.x;
    const int lq  = tid & (D4 - 1);                 // channel-quad index 0..63
    const int l   = (blockIdx.x << 2) + (tid >> 6); // position 0..16383
    const int d0  = lq << 2;                        // first channel of this quad

    const int row = l >> 7;        // l / 128
    const int col = l & (W - 1);   // l % 128

    // All 4 channels in this quad live in one half (split at d=128).
    const bool rhalf = (d0 < 128);
    const float pos  = rhalf ? (float)row : (float)col;
    const int   j0   = rhalf ? (d0 >> 1) : ((d0 - 128) >> 1);

    // freq[j] = exp(j * (-2*ln(10000)/128))
    const float KF = -0.14391156831212787f;  // -2*ln(10000)/128
    const float f0 = expf((float)j0 * KF);
    const float f1 = expf((float)(j0 + 1) * KF);

    float s0, c0, s1, c1;
    sincosf(pos * f0, &s0, &c0);
    sincosf(pos * f1, &s1, &c1);
    const float4 pe = make_float4(s0, c0, s1, c1);

    // 32-bit addressing: max offset 128 MiB of float4 < 2^31.
    const unsigned base = (unsigned)l * D4 + (unsigned)lq;

    if (b == 8) {
        // All 8 loads in flight before any store (MLP=8 per thread).
        float4 v[8];
        #pragma unroll
        for (int bi = 0; bi < 8; bi++)
            v[bi] = x[base + bi * STRIDE4];
        #pragma unroll
        for (int bi = 0; bi < 8; bi++) {
            v[bi].x += pe.x; v[bi].y += pe.y; v[bi].z += pe.z; v[bi].w += pe.w;
            out[base + bi * STRIDE4] = v[bi];
        }
    } else {
        for (int bi = 0; bi < b; bi++) {
            float4 v = x[base + bi * STRIDE4];
            v.x += pe.x; v.y += pe.y; v.z += pe.z; v.w += pe.w;
            out[base + bi * STRIDE4] = v;
        }
    }
}

extern "C" void kernel_launch(void* const* d_in, const int* in_sizes, int n_in,
                              void* d_out, int out_size)
{
    const float4* x  = (const float4*)d_in[0];
    float4* out      = (float4*)d_out;
    const int n      = in_sizes[0];          // total elements of x
    const int b      = n / (L * D);          // batch size (8 here)

    const dim3 grid(L / POS_PER_BLOCK);      // 4096 blocks
    const dim3 block(256);
    pe_add_kernel<<<grid, block>>>(x, out, b);
}